// round 16
// baseline (speedup 1.0000x reference)
#include <cuda_runtime.h>
#include <math.h>

// ---------------- problem constants ----------------
constexpr int T_    = 2048;
constexpr int H_    = 1024;
constexpr int NH_   = 16;
constexpr int NKV_  = 4;
constexpr int HD_   = 64;
constexpr int E_    = 32;
constexpr int TOPK_ = 4;
constexpr int NG_   = 4;
constexpr int IM_   = 384;
constexpr int ISH_  = 384;
constexpr int QW_   = (NH_ + 2 * NKV_) * HD_;   // 1536
constexpr float EPS_ = 1e-5f;

// ---------------- scratch (44 MiB; aliased across phases — DO NOT GROW) ----------------
__device__ float g_hid[T_ * H_];                          // 8 MiB
__device__ float g_qkv[T_ * QW_];                         // 12 MiB
__device__ float g_gu [T_ * TOPK_ * 2 * IM_];             // 24 MiB
__device__ int   g_ids   [T_ * TOPK_];
__device__ float g_w     [T_ * TOPK_];
__device__ int   g_counts[E_];
__device__ int   g_offsets[E_ + 1];
__device__ int   g_cursor[E_];
__device__ int   g_tok   [T_ * TOPK_];
__device__ float g_wslot [T_ * TOPK_];

#define HID2   g_qkv                                   /* post-attn normed hidden */
#define GUS    g_gu                                    /* shared-expert pre-act   */
#define ROUTED g_hid                                   /* routed-expert accum     */
#define RES_FB (g_gu + 4194304)                        /* residual fallback       */

__constant__ float c_ropeinv[16] = {
    1.0f,                 0.5623413251903491f,  0.31622776601683794f, 0.17782794100389229f,
    0.1f,                 0.05623413251903491f, 0.031622776601683794f,0.017782794100389228f,
    0.01f,                0.005623413251903491f,0.0031622776601683794f,0.0017782794100389228f,
    0.001f,               0.0005623413251903491f,0.00031622776601683794f,0.00017782794100389227f
};

// ---------------- helpers ----------------
#define Z4 make_float4(0.f, 0.f, 0.f, 0.f)
typedef unsigned long long u64;

__device__ __forceinline__ float dot4(float4 a, float4 b) {
    return fmaf(a.x, b.x, fmaf(a.y, b.y, fmaf(a.z, b.z, a.w * b.w)));
}
__device__ __forceinline__ float4 add4(float4 a, float4 b) {
    return make_float4(a.x + b.x, a.y + b.y, a.z + b.z, a.w + b.w);
}
__device__ __forceinline__ float silu_mul(float g, float u) {
    return (g / (1.f + __expf(-g))) * u;
}
__device__ __forceinline__ float4 silu4(float4 g, float4 u) {
    return make_float4(silu_mul(g.x, u.x), silu_mul(g.y, u.y),
                       silu_mul(g.z, u.z), silu_mul(g.w, u.w));
}
// ---- packed f32x2 ops ----
__device__ __forceinline__ void fma2p(u64& d, u64 a, u64 b) {
    asm("fma.rn.f32x2 %0, %1, %2, %0;" : "+l"(d) : "l"(a), "l"(b));
}
__device__ __forceinline__ u64 pack2(float x) {
    u64 r; unsigned int bb = __float_as_uint(x);
    asm("mov.b64 %0, {%1, %2};" : "=l"(r) : "r"(bb), "r"(bb));
    return r;
}
__device__ __forceinline__ u64 pack2f(float lo, float hi) {
    u64 r;
    asm("mov.b64 %0, {%1, %2};" : "=l"(r)
        : "r"(__float_as_uint(lo)), "r"(__float_as_uint(hi)));
    return r;
}
__device__ __forceinline__ float2 unpack2(u64 v) {
    unsigned int lo, hi;
    asm("mov.b64 {%0, %1}, %2;" : "=r"(lo), "=r"(hi) : "l"(v));
    return make_float2(__uint_as_float(lo), __uint_as_float(hi));
}
// ---- cp.async (LDGSTS) ----
__device__ __forceinline__ unsigned scvta(const void* p) {
    return (unsigned)__cvta_generic_to_shared(p);
}
__device__ __forceinline__ void cp_async16(unsigned saddr, const void* gptr) {
    asm volatile("cp.async.ca.shared.global [%0], [%1], 16;" :: "r"(saddr), "l"(gptr));
}
#define CP_COMMIT asm volatile("cp.async.commit_group;" ::: "memory");
#define CP_WAIT0  asm volatile("cp.async.wait_group 0;" ::: "memory");

// ======== pipelined 128x64x32 SGEMM pieces (double-buffered, 1 sync/step) ========
// Dynamic smem: As[2][32][128] + Bs[2][32][64] = 49152 B.
#define GEMM_ACCUM \
    u64 c00=0,c01=0,c02=0,c03=0,c10=0,c11=0,c12=0,c13=0, \
        c20=0,c21=0,c22=0,c23=0,c30=0,c31=0,c32=0,c33=0;

#define GEMM_COMPUTE(Ab, Bb) \
    _Pragma("unroll") \
    for (int kk = 0; kk < 32; kk++) { \
        const u64* ap = reinterpret_cast<const u64*>((Ab) + kk * 128 + (ty << 3)); \
        u64 a0 = ap[0], a1 = ap[1], a2 = ap[2], a3 = ap[3]; \
        float4 bf = *reinterpret_cast<const float4*>((Bb) + kk * 64 + (tx << 2)); \
        u64 b0 = pack2(bf.x), b1 = pack2(bf.y), b2 = pack2(bf.z), b3 = pack2(bf.w); \
        fma2p(c00,a0,b0); fma2p(c01,a0,b1); fma2p(c02,a0,b2); fma2p(c03,a0,b3); \
        fma2p(c10,a1,b0); fma2p(c11,a1,b1); fma2p(c12,a1,b2); fma2p(c13,a1,b3); \
        fma2p(c20,a2,b0); fma2p(c21,a2,b1); fma2p(c22,a2,b2); fma2p(c23,a2,b3); \
        fma2p(c30,a3,b0); fma2p(c31,a3,b1); fma2p(c32,a3,b2); fma2p(c33,a3,b3); \
    }

#define STS_A(Ab) { \
    (Ab)[(ac + 0) * 128 + ar] = av0.x; (Ab)[(ac + 1) * 128 + ar] = av0.y; \
    (Ab)[(ac + 2) * 128 + ar] = av0.z; (Ab)[(ac + 3) * 128 + ar] = av0.w; \
    (Ab)[(ac + 4) * 128 + ar] = av1.x; (Ab)[(ac + 5) * 128 + ar] = av1.y; \
    (Ab)[(ac + 6) * 128 + ar] = av1.z; (Ab)[(ac + 7) * 128 + ar] = av1.w; \
    (Ab)[(ac + 8) * 128 + ar] = av2.x; (Ab)[(ac + 9) * 128 + ar] = av2.y; \
    (Ab)[(ac +10) * 128 + ar] = av2.z; (Ab)[(ac +11) * 128 + ar] = av2.w; \
    (Ab)[(ac +12) * 128 + ar] = av3.x; (Ab)[(ac +13) * 128 + ar] = av3.y; \
    (Ab)[(ac +14) * 128 + ar] = av3.z; (Ab)[(ac +15) * 128 + ar] = av3.w; }

#define GEMM_EPILOGUE(STORE_ROW) { \
    int rbase = m0 + (ty << 3); \
    { float2 x0=unpack2(c00), x1=unpack2(c01), x2=unpack2(c02), x3=unpack2(c03); \
      STORE_ROW(rbase + 0, make_float4(x0.x,x1.x,x2.x,x3.x)) \
      STORE_ROW(rbase + 1, make_float4(x0.y,x1.y,x2.y,x3.y)) } \
    { float2 x0=unpack2(c10), x1=unpack2(c11), x2=unpack2(c12), x3=unpack2(c13); \
      STORE_ROW(rbase + 2, make_float4(x0.x,x1.x,x2.x,x3.x)) \
      STORE_ROW(rbase + 3, make_float4(x0.y,x1.y,x2.y,x3.y)) } \
    { float2 x0=unpack2(c20), x1=unpack2(c21), x2=unpack2(c22), x3=unpack2(c23); \
      STORE_ROW(rbase + 4, make_float4(x0.x,x1.x,x2.x,x3.x)) \
      STORE_ROW(rbase + 5, make_float4(x0.y,x1.y,x2.y,x3.y)) } \
    { float2 x0=unpack2(c30), x1=unpack2(c31), x2=unpack2(c32), x3=unpack2(c33); \
      STORE_ROW(rbase + 6, make_float4(x0.x,x1.x,x2.x,x3.x)) \
      STORE_ROW(rbase + 7, make_float4(x0.y,x1.y,x2.y,x3.y)) } \
}

#define GEMM_PIPE_DECLS \
    extern __shared__ __align__(16) float dynsm[]; \
    float* A0 = dynsm;               /* [32][128] */ \
    float* A1 = dynsm + 4096; \
    float* B0 = dynsm + 8192;        /* [32][64]  */ \
    float* B1 = dynsm + 8192 + 2048; \
    int tid = threadIdx.x; \
    int tx = tid & 15, ty = tid >> 4; \
    int ar = tid >> 1, ac = (tid & 1) << 4; \
    int br = tid >> 3, bc = (tid & 7) << 3; \
    unsigned sB0a = scvta(B0 + br * 64 + bc), sB0b = sB0a + 16; \
    unsigned sB1a = scvta(B1 + br * 64 + bc), sB1b = sB1a + 16; \
    GEMM_ACCUM \
    float4 av0, av1, av2, av3;

#define GEMM_PIPE_LOOP(LOADA, BPTR, KCONST) \
    LOADA(0) \
    cp_async16(sB0a, (BPTR) + (size_t)br * N + n0 + bc); \
    cp_async16(sB0b, (BPTR) + (size_t)br * N + n0 + bc + 4); \
    CP_COMMIT \
    STS_A(A0) \
    { \
        int cur = 0; \
        for (int k0 = 0; k0 < (KCONST); k0 += 32) { \
            CP_WAIT0 \
            __syncthreads(); \
            bool has = (k0 + 32) < (KCONST); \
            if (has) { \
                LOADA(k0 + 32) \
                cp_async16(cur ? sB0a : sB1a, \
                           (BPTR) + (size_t)(k0 + 32 + br) * N + n0 + bc); \
                cp_async16(cur ? sB0b : sB1b, \
                           (BPTR) + (size_t)(k0 + 32 + br) * N + n0 + bc + 4); \
                CP_COMMIT \
            } \
            if (cur) { GEMM_COMPUTE(A1, B1) } else { GEMM_COMPUTE(A0, B0) } \
            if (has) { if (cur) { STS_A(A0) } else { STS_A(A1) } } \
            cur ^= 1; \
        } \
    }

constexpr int GEMM_SMEM_BYTES = (8192 + 4096) * 4;   // 49152

// ---------------- generic direct SGEMM: C = A@B (+D) ----------------
template <bool ADD>
__device__ __forceinline__ void gemm_body(const float* __restrict__ A, const float* __restrict__ B,
                                          float* __restrict__ C, const float* __restrict__ D,
                                          int M, int N, int K) {
    int n0 = blockIdx.x * 64;
    int m0 = blockIdx.y * 128;
    if (m0 >= M) return;
    GEMM_PIPE_DECLS
    #define LOADA_G(k0v) { \
        av0 = Z4; av1 = Z4; av2 = Z4; av3 = Z4; \
        if (m0 + ar < M) { \
            const float* arow = A + (size_t)(m0 + ar) * K + (k0v) + ac; \
            av0 = *reinterpret_cast<const float4*>(arow); \
            av1 = *reinterpret_cast<const float4*>(arow + 4); \
            av2 = *reinterpret_cast<const float4*>(arow + 8); \
            av3 = *reinterpret_cast<const float4*>(arow + 12); } }
    GEMM_PIPE_LOOP(LOADA_G, B, K)
    #undef LOADA_G
    int cc = n0 + (tx << 2);
    #define SROW(r, v) { int rr = (r); if (rr < M) { \
        float4 vv = v; \
        if (ADD) vv = add4(vv, *reinterpret_cast<const float4*>(D + (size_t)rr * N + cc)); \
        *reinterpret_cast<float4*>(C + (size_t)rr * N + cc) = vv; } }
    GEMM_EPILOGUE(SROW)
    #undef SROW
}

__global__ __launch_bounds__(256) void gemm_qkv_kernel(const float* __restrict__ Wqkv) {
    gemm_body<false>(g_hid, Wqkv, g_qkv, nullptr, T_, QW_, H_);
}
__global__ __launch_bounds__(256) void gemm_o_kernel(const float* __restrict__ Wo, float* __restrict__ p) {
    float* resid = (p != nullptr) ? p : RES_FB;
    gemm_body<true>(g_hid, Wo, resid, resid, T_, H_, H_);
}
__global__ __launch_bounds__(256) void gemm_gus_kernel(const float* __restrict__ Wgu_sh) {
    gemm_body<false>(HID2, Wgu_sh, GUS, nullptr, T_, 2 * ISH_, H_);
}

// ---------------- MoE GEMM1: gu[slot,768] = HID2[tok] @ Wgu[e] ----------------
__global__ __launch_bounds__(256)
void moe_gemm1_kernel(const float* __restrict__ Wgu) {
    int e = blockIdx.z;
    int base = g_offsets[e];
    int ne = g_offsets[e + 1] - base;
    int m0 = blockIdx.y * 128;
    if (m0 >= ne) return;
    int n0 = blockIdx.x * 64;
    const int N = 2 * IM_, K = H_;
    const float* B = Wgu + (size_t)e * K * N;
    __shared__ int rowtok[128];
    if (threadIdx.x < 128)
        rowtok[threadIdx.x] = (m0 + threadIdx.x < ne) ? g_tok[base + m0 + threadIdx.x] : -1;
    __syncthreads();
    GEMM_PIPE_DECLS
    #define LOADA_M1(k0v) { \
        int tk = rowtok[ar]; \
        av0 = Z4; av1 = Z4; av2 = Z4; av3 = Z4; \
        if (tk >= 0) { \
            const float* arow = HID2 + (size_t)tk * K + (k0v) + ac; \
            av0 = *reinterpret_cast<const float4*>(arow); \
            av1 = *reinterpret_cast<const float4*>(arow + 4); \
            av2 = *reinterpret_cast<const float4*>(arow + 8); \
            av3 = *reinterpret_cast<const float4*>(arow + 12); } }
    GEMM_PIPE_LOOP(LOADA_M1, B, K)
    #undef LOADA_M1
    int cc = n0 + (tx << 2);
    #define SROW(r, v) { int rr = (r); if (rr < ne) { \
        *reinterpret_cast<float4*>(g_gu + (size_t)(base + rr) * N + cc) = v; } }
    GEMM_EPILOGUE(SROW)
    #undef SROW
}

// ---- MoE GEMM2: routed[tok] += w * (silu(gu[:,:384])*gu[:,384:]) @ Wd[e] ----
__global__ __launch_bounds__(256)
void moe_gemm2_kernel(const float* __restrict__ Wd) {
    int e = blockIdx.z;
    int base = g_offsets[e];
    int ne = g_offsets[e + 1] - base;
    int m0 = blockIdx.y * 128;
    if (m0 >= ne) return;
    int n0 = blockIdx.x * 64;
    const int N = H_, K = IM_;
    const float* B = Wd + (size_t)e * K * N;
    __shared__ int   s_tok[128];
    __shared__ float s_wt[128];
    if (threadIdx.x < 128) {
        bool v = (m0 + threadIdx.x < ne);
        s_tok[threadIdx.x] = v ? g_tok[base + m0 + threadIdx.x] : -1;
        s_wt[threadIdx.x]  = v ? g_wslot[base + m0 + threadIdx.x] : 0.f;
    }
    __syncthreads();
    GEMM_PIPE_DECLS
    #define LOADA_M2(k0v) { \
        av0 = Z4; av1 = Z4; av2 = Z4; av3 = Z4; \
        if (m0 + ar < ne) { \
            const float* gub = g_gu + (size_t)(base + m0 + ar) * (2 * IM_); \
            float4 gg0 = *reinterpret_cast<const float4*>(gub + (k0v) + ac); \
            float4 gg1 = *reinterpret_cast<const float4*>(gub + (k0v) + ac + 4); \
            float4 gg2 = *reinterpret_cast<const float4*>(gub + (k0v) + ac + 8); \
            float4 gg3 = *reinterpret_cast<const float4*>(gub + (k0v) + ac + 12); \
            float4 uu0 = *reinterpret_cast<const float4*>(gub + IM_ + (k0v) + ac); \
            float4 uu1 = *reinterpret_cast<const float4*>(gub + IM_ + (k0v) + ac + 4); \
            float4 uu2 = *reinterpret_cast<const float4*>(gub + IM_ + (k0v) + ac + 8); \
            float4 uu3 = *reinterpret_cast<const float4*>(gub + IM_ + (k0v) + ac + 12); \
            av0 = silu4(gg0, uu0); av1 = silu4(gg1, uu1); \
            av2 = silu4(gg2, uu2); av3 = silu4(gg3, uu3); } }
    GEMM_PIPE_LOOP(LOADA_M2, B, K)
    #undef LOADA_M2
    int cc = n0 + (tx << 2);
    #define SROW(r, v) { int slo = (r) - m0; \
        if (m0 + slo < ne) { \
            int tok = s_tok[slo]; float w = s_wt[slo]; float4 vv = v; \
            float* dst = ROUTED + (size_t)tok * N + cc; \
            atomicAdd(dst + 0, w * vv.x); atomicAdd(dst + 1, w * vv.y); \
            atomicAdd(dst + 2, w * vv.z); atomicAdd(dst + 3, w * vv.w); } }
    GEMM_EPILOGUE(SROW)
    #undef SROW
}

// ---- final GEMM: out = (silu(gus)*u) @ Wd_sh + routed ----
__global__ __launch_bounds__(256)
void gemm_final_kernel(const float* __restrict__ Wd_sh, float* __restrict__ out) {
    const int N = H_, K = ISH_;
    int n0 = blockIdx.x * 64;
    int m0 = blockIdx.y * 128;
    GEMM_PIPE_DECLS
    #define LOADA_F(k0v) { \
        const float* gub = GUS + (size_t)(m0 + ar) * (2 * ISH_); \
        float4 gg0 = *reinterpret_cast<const float4*>(gub + (k0v) + ac); \
        float4 gg1 = *reinterpret_cast<const float4*>(gub + (k0v) + ac + 4); \
        float4 gg2 = *reinterpret_cast<const float4*>(gub + (k0v) + ac + 8); \
        float4 gg3 = *reinterpret_cast<const float4*>(gub + (k0v) + ac + 12); \
        float4 uu0 = *reinterpret_cast<const float4*>(gub + ISH_ + (k0v) + ac); \
        float4 uu1 = *reinterpret_cast<const float4*>(gub + ISH_ + (k0v) + ac + 4); \
        float4 uu2 = *reinterpret_cast<const float4*>(gub + ISH_ + (k0v) + ac + 8); \
        float4 uu3 = *reinterpret_cast<const float4*>(gub + ISH_ + (k0v) + ac + 12); \
        av0 = silu4(gg0, uu0); av1 = silu4(gg1, uu1); \
        av2 = silu4(gg2, uu2); av3 = silu4(gg3, uu3); }
    GEMM_PIPE_LOOP(LOADA_F, Wd_sh, K)
    #undef LOADA_F
    int cc = n0 + (tx << 2);
    #define SROW(r, v) { int rr = (r); \
        float4 vv = add4(v, *reinterpret_cast<const float4*>(ROUTED + (size_t)rr * N + cc)); \
        *reinterpret_cast<float4*>(out + (size_t)rr * N + cc) = vv; }
    GEMM_EPILOGUE(SROW)
    #undef SROW
}

// ---------------- step 1: residual add + input RMSNorm ----------------
__global__ void add_rms_kernel(const float* __restrict__ a, const float* __restrict__ b,
                               const float* __restrict__ w, float* __restrict__ p) {
    float* resid = (p != nullptr) ? p : RES_FB;
    int t = blockIdx.x;
    int i = threadIdx.x;
    float4 av = reinterpret_cast<const float4*>(a + (size_t)t * H_)[i];
    float4 bv = reinterpret_cast<const float4*>(b + (size_t)t * H_)[i];
    float4 r  = add4(av, bv);
    reinterpret_cast<float4*>(resid + (size_t)t * H_)[i] = r;
    float ss = dot4(r, r);
    __shared__ float red[8];
    __shared__ float s_rs;
    for (int o = 16; o > 0; o >>= 1) ss += __shfl_down_sync(0xffffffffu, ss, o);
    if ((threadIdx.x & 31) == 0) red[threadIdx.x >> 5] = ss;
    __syncthreads();
    if (threadIdx.x == 0) {
        float tot = 0.f;
        #pragma unroll
        for (int k = 0; k < 8; k++) tot += red[k];
        s_rs = rsqrtf(tot / (float)H_ + EPS_);
    }
    __syncthreads();
    float rs = s_rs;
    float4 wv = reinterpret_cast<const float4*>(w)[i];
    float4 o4 = make_float4(r.x * rs * wv.x, r.y * rs * wv.y, r.z * rs * wv.z, r.w * rs * wv.w);
    reinterpret_cast<float4*>(g_hid + (size_t)t * H_)[i] = o4;
}

// ---------------- step 6: post-attn RMSNorm ----------------
__global__ void rms2_kernel(const float* __restrict__ p, const float* __restrict__ w) {
    const float* x = (p != nullptr) ? p : RES_FB;
    int t = blockIdx.x;
    int i = threadIdx.x;
    float4 r = reinterpret_cast<const float4*>(x + (size_t)t * H_)[i];
    float ss = dot4(r, r);
    __shared__ float red[8];
    __shared__ float s_rs;
    for (int o = 16; o > 0; o >>= 1) ss += __shfl_down_sync(0xffffffffu, ss, o);
    if ((threadIdx.x & 31) == 0) red[threadIdx.x >> 5] = ss;
    __syncthreads();
    if (threadIdx.x == 0) {
        float tot = 0.f;
        #pragma unroll
        for (int k = 0; k < 8; k++) tot += red[k];
        s_rs = rsqrtf(tot / (float)H_ + EPS_);
    }
    __syncthreads();
    float rs = s_rs;
    float4 wv = reinterpret_cast<const float4*>(w)[i];
    float4 o4 = make_float4(r.x * rs * wv.x, r.y * rs * wv.y, r.z * rs * wv.z, r.w * rs * wv.w);
    reinterpret_cast<float4*>(HID2 + (size_t)t * H_)[i] = o4;
}

// ---------------- step 3: QK RMSNorm + RoPE ----------------
__global__ void qknorm_rope_kernel(const int* __restrict__ positions,
                                   const float* __restrict__ qw,
                                   const float* __restrict__ kw) {
    int warp = (blockIdx.x * blockDim.x + threadIdx.x) >> 5;
    int lane = threadIdx.x & 31;
    int total = T_ * (NH_ + NKV_);
    if (warp >= total) return;
    int t = warp / (NH_ + NKV_);
    int h = warp % (NH_ + NKV_);
    float* base = g_qkv + (size_t)t * QW_ + h * HD_;
    float xa = base[lane];
    float xb = base[lane + 32];
    float ss = xa * xa + xb * xb;
    for (int o = 16; o > 0; o >>= 1) ss += __shfl_xor_sync(0xffffffffu, ss, o);
    float rs = rsqrtf(ss / (float)HD_ + EPS_);
    const float* w = (h < NH_) ? qw : kw;
    xa *= rs * w[lane];
    xb *= rs * w[lane + 32];
    int i = lane & 15;
    float ang = (float)positions[t] * c_ropeinv[i];
    float kf = __int2float_rn(__float2int_rn(ang * 0.15915494309189535f));
    float r = fmaf(kf, -6.28125f, ang);
    r = fmaf(kf, -1.9353071795864769e-3f, r);
    float c = __cosf(r);
    float s = __sinf(r);
    float partner = __shfl_xor_sync(0xffffffffu, xa, 16);
    float res = (lane < 16) ? (xa * c - partner * s) : (partner * s + xa * c);
    base[lane] = res;
    base[lane + 32] = xb;
}

// ---------------- step 4: causal attention — two tiled GEMMs (unchanged from R15) ------
__global__ __launch_bounds__(256, 2)
void attn_kernel() {
    extern __shared__ float sm[];
    float* Qs = sm;
    float* Ks = sm + 8192;
    float* Vs = sm + 12288;
    u64*   Pp = reinterpret_cast<u64*>(sm + 16384);

    int h  = blockIdx.x;
    int qb = (gridDim.y - 1) - blockIdx.y;
    int kh = h >> 2;
    int tid = threadIdx.x;
    int tx = tid & 15, ty = tid >> 4;
    int qbase = qb * 128;

    {
        int q  = tid >> 1;
        int dh = (tid & 1) << 5;
        const float4* src = reinterpret_cast<const float4*>(
            g_qkv + (size_t)(qbase + q) * QW_ + h * HD_ + dh);
        #pragma unroll
        for (int i = 0; i < 8; i++) {
            float4 v = src[i];
            int d = dh + (i << 2);
            Qs[(d+0)*128 + q] = v.x; Qs[(d+1)*128 + q] = v.y;
            Qs[(d+2)*128 + q] = v.z; Qs[(d+3)*128 + q] = v.w;
        }
    }
    u64 o00=0,o01=0,o02=0,o03=0,o10=0,o11=0,o12=0,o13=0,
        o20=0,o21=0,o22=0,o23=0,o30=0,o31=0,o32=0,o33=0;
    float l0=0,l1=0,l2=0,l3=0,l4=0,l5=0,l6=0,l7=0;

    int ntiles = 2 * qb + 2;
    for (int tile = 0; tile < ntiles; tile++) {
        int s0 = tile * 64;
        __syncthreads();
        {
            int kl = tid & 63;
            int db = (tid >> 6) << 4;
            const float* kr = g_qkv + (size_t)(s0 + kl) * QW_ + NH_ * HD_ + kh * HD_ + db;
            #pragma unroll
            for (int i = 0; i < 4; i++) {
                float4 v = *reinterpret_cast<const float4*>(kr + (i << 2));
                int d = db + (i << 2);
                Ks[(d+0)*64+kl]=v.x; Ks[(d+1)*64+kl]=v.y; Ks[(d+2)*64+kl]=v.z; Ks[(d+3)*64+kl]=v.w;
            }
            const float* vr = kr + NKV_ * HD_;
            #pragma unroll
            for (int i = 0; i < 4; i++) {
                float4 v = *reinterpret_cast<const float4*>(vr + (i << 2));
                *reinterpret_cast<float4*>(&Vs[kl * 64 + db + (i << 2)]) = v;
            }
        }
        __syncthreads();
        u64 s00=0,s01=0,s02=0,s03=0,s10=0,s11=0,s12=0,s13=0,
            s20=0,s21=0,s22=0,s23=0,s30=0,s31=0,s32=0,s33=0;
        #pragma unroll 4
        for (int kk = 0; kk < 64; kk++) {
            const u64* ap = reinterpret_cast<const u64*>(Qs + kk * 128 + (ty << 3));
            u64 a0 = ap[0], a1 = ap[1], a2 = ap[2], a3 = ap[3];
            const float4 bf = *reinterpret_cast<const float4*>(Ks + kk * 64 + (tx << 2));
            u64 b0 = pack2(bf.x), b1 = pack2(bf.y), b2 = pack2(bf.z), b3 = pack2(bf.w);
            fma2p(s00,a0,b0); fma2p(s01,a0,b1); fma2p(s02,a0,b2); fma2p(s03,a0,b3);
            fma2p(s10,a1,b0); fma2p(s11,a1,b1); fma2p(s12,a1,b2); fma2p(s13,a1,b3);
            fma2p(s20,a2,b0); fma2p(s21,a2,b1); fma2p(s22,a2,b2); fma2p(s23,a2,b3);
            fma2p(s30,a3,b0); fma2p(s31,a3,b1); fma2p(s32,a3,b2); fma2p(s33,a3,b3);
        }
        int kg = s0 + (tx << 2);
        #define DOQP(qp, sA, sB, sC, sD, rA, rB) { \
            int qg0 = qbase + (ty << 3) + 2 * qp; int qg1 = qg0 + 1; \
            float2 e0 = unpack2(sA), e1 = unpack2(sB), e2 = unpack2(sC), e3 = unpack2(sD); \
            float p00 = (kg+0 <= qg0) ? __expf(fmaf(e0.x, 0.125f, -8.f)) : 0.f; \
            float p01 = (kg+1 <= qg0) ? __expf(fmaf(e1.x, 0.125f, -8.f)) : 0.f; \
            float p02 = (kg+2 <= qg0) ? __expf(fmaf(e2.x, 0.125f, -8.f)) : 0.f; \
            float p03 = (kg+3 <= qg0) ? __expf(fmaf(e3.x, 0.125f, -8.f)) : 0.f; \
            float p10 = (kg+0 <= qg1) ? __expf(fmaf(e0.y, 0.125f, -8.f)) : 0.f; \
            float p11 = (kg+1 <= qg1) ? __expf(fmaf(e1.y, 0.125f, -8.f)) : 0.f; \
            float p12 = (kg+2 <= qg1) ? __expf(fmaf(e2.y, 0.125f, -8.f)) : 0.f; \
            float p13 = (kg+3 <= qg1) ? __expf(fmaf(e3.y, 0.125f, -8.f)) : 0.f; \
            rA += (p00 + p01) + (p02 + p03); \
            rB += (p10 + p11) + (p12 + p13); \
            u64* dst = Pp + ((ty << 2) + qp) * 68 + (tx << 2); \
            dst[0] = pack2f(p00, p10); dst[1] = pack2f(p01, p11); \
            dst[2] = pack2f(p02, p12); dst[3] = pack2f(p03, p13); }
        float r0=0,r1=0,r2=0,r3=0,r4=0,r5=0,r6=0,r7=0;
        DOQP(0, s00, s01, s02, s03, r0, r1)
        DOQP(1, s10, s11, s12, s13, r2, r3)
        DOQP(2, s20, s21, s22, s23, r4, r5)
        DOQP(3, s30, s31, s32, s33, r6, r7)
        #undef DOQP
        #pragma unroll
        for (int off = 1; off < 16; off <<= 1) {
            r0 += __shfl_xor_sync(0xffffffffu, r0, off);
            r1 += __shfl_xor_sync(0xffffffffu, r1, off);
            r2 += __shfl_xor_sync(0xffffffffu, r2, off);
            r3 += __shfl_xor_sync(0xffffffffu, r3, off);
            r4 += __shfl_xor_sync(0xffffffffu, r4, off);
            r5 += __shfl_xor_sync(0xffffffffu, r5, off);
            r6 += __shfl_xor_sync(0xffffffffu, r6, off);
            r7 += __shfl_xor_sync(0xffffffffu, r7, off);
        }
        l0 += r0; l1 += r1; l2 += r2; l3 += r3;
        l4 += r4; l5 += r5; l6 += r6; l7 += r7;
        __syncthreads();
        #pragma unroll 4
        for (int s = 0; s < 64; s++) {
            u64 a0 = Pp[((ty << 2) + 0) * 68 + s];
            u64 a1 = Pp[((ty << 2) + 1) * 68 + s];
            u64 a2 = Pp[((ty << 2) + 2) * 68 + s];
            u64 a3 = Pp[((ty << 2) + 3) * 68 + s];
            const float4 vf = *reinterpret_cast<const float4*>(&Vs[s * 64 + (tx << 2)]);
            u64 b0 = pack2(vf.x), b1 = pack2(vf.y), b2 = pack2(vf.z), b3 = pack2(vf.w);
            fma2p(o00,a0,b0); fma2p(o01,a0,b1); fma2p(o02,a0,b2); fma2p(o03,a0,b3);
            fma2p(o10,a1,b0); fma2p(o11,a1,b1); fma2p(o12,a1,b2); fma2p(o13,a1,b3);
            fma2p(o20,a2,b0); fma2p(o21,a2,b1); fma2p(o22,a2,b2); fma2p(o23,a2,b3);
            fma2p(o30,a3,b0); fma2p(o31,a3,b1); fma2p(o32,a3,b2); fma2p(o33,a3,b3);
        }
    }
    float i0 = 1.f/l0, i1 = 1.f/l1, i2 = 1.f/l2, i3 = 1.f/l3;
    float i4 = 1.f/l4, i5 = 1.f/l5, i6 = 1.f/l6, i7 = 1.f/l7;
    int cbase = h * HD_ + (tx << 2);
    #define OUTQP(qp, uA, uB, uC, uD, iA, iB) { \
        float2 e0 = unpack2(uA), e1 = unpack2(uB), e2 = unpack2(uC), e3 = unpack2(uD); \
        int rA = qbase + (ty << 3) + 2 * qp; \
        *reinterpret_cast<float4*>(g_hid + (size_t)rA * H_ + cbase) = \
            make_float4(e0.x * iA, e1.x * iA, e2.x * iA, e3.x * iA); \
        *reinterpret_cast<float4*>(g_hid + (size_t)(rA + 1) * H_ + cbase) = \
            make_float4(e0.y * iB, e1.y * iB, e2.y * iB, e3.y * iB); }
    OUTQP(0, o00, o01, o02, o03, i0, i1)
    OUTQP(1, o10, o11, o12, o13, i2, i3)
    OUTQP(2, o20, o21, o22, o23, i4, i5)
    OUTQP(3, o30, o31, o32, o33, i6, i7)
    #undef OUTQP
}

// ---------------- router / routing infrastructure ----------------
__global__ void router_kernel(const float* __restrict__ Wg, const float* __restrict__ gbias) {
    int t = blockIdx.x;
    int lane = threadIdx.x;
    __shared__ float hsh[H_];
    for (int i = lane; i < H_; i += 32) hsh[i] = HID2[(size_t)t * H_ + i];
    __syncwarp();
    float acc = 0.f;
    for (int hh = 0; hh < H_; hh++) acc = fmaf(hsh[hh], Wg[hh * E_ + lane], acc);
    float scr = 1.f / (1.f + __expf(-acc));
    float sfc = scr + gbias[lane];
    __shared__ float s_scr[E_], s_sfc[E_], s_tmp[E_], s_gs[NG_];
    s_scr[lane] = scr; s_sfc[lane] = sfc;
    __syncwarp();
    if (lane == 0) {
        for (int g = 0; g < NG_; g++) {
            float m1 = -INFINITY, m2 = -INFINITY;
            for (int j = 0; j < E_ / NG_; j++) {
                float v = s_sfc[g * (E_ / NG_) + j];
                if (v > m1) { m2 = m1; m1 = v; } else if (v > m2) m2 = v;
            }
            s_gs[g] = m1 + m2;
        }
        int g1 = 0;
        for (int g = 1; g < NG_; g++) if (s_gs[g] > s_gs[g1]) g1 = g;
        s_gs[g1] = -INFINITY;
        int g2 = 0;
        for (int g = 1; g < NG_; g++) if (s_gs[g] > s_gs[g2]) g2 = g;
        for (int e = 0; e < E_; e++) {
            int g = e / (E_ / NG_);
            s_tmp[e] = (g == g1 || g == g2) ? s_sfc[e] : -INFINITY;
        }
        float wsum = 0.f;
        #pragma unroll
        for (int k = 0; k < TOPK_; k++) {
            int best = 0; float bv = s_tmp[0];
            for (int e = 1; e < E_; e++) if (s_tmp[e] > bv) { bv = s_tmp[e]; best = e; }
            s_tmp[best] = -INFINITY;
            wsum += s_scr[best];
            g_ids[t * TOPK_ + k] = best;
            atomicAdd(&g_counts[best], 1);
        }
        float rw = 1.f / wsum;
        #pragma unroll
        for (int k = 0; k < TOPK_; k++)
            g_w[t * TOPK_ + k] = s_scr[g_ids[t * TOPK_ + k]] * rw;
    }
}

__global__ void init_kernel() {
    int i = threadIdx.x;
    if (i < E_) { g_counts[i] = 0; g_cursor[i] = 0; }
}

__global__ void prefix_kernel() {
    if (threadIdx.x == 0) {
        int s = 0;
        for (int e = 0; e < E_; e++) { g_offsets[e] = s; s += g_counts[e]; }
        g_offsets[E_] = s;
    }
}

__global__ void scatter_kernel() {
    int t = blockIdx.x * blockDim.x + threadIdx.x;
    if (t >= T_) return;
    #pragma unroll
    for (int k = 0; k < TOPK_; k++) {
        int e = g_ids[t * TOPK_ + k];
        int p = atomicAdd(&g_cursor[e], 1);
        int slot = g_offsets[e] + p;
        g_tok[slot] = t;
        g_wslot[slot] = g_w[t * TOPK_ + k];
    }
}

__global__ void zero_routed_kernel() {
    int i = blockIdx.x * blockDim.x + threadIdx.x;
    reinterpret_cast<float4*>(ROUTED)[i] = Z4;
}

// ---------------- host launch ----------------
extern "C" void kernel_launch(void* const* d_in, const int* in_sizes, int n_in,
                              void* d_out, int out_size) {
    const float* hs     = (const float*)d_in[0];
    const float* res    = (const float*)d_in[1];
    const float* in_w   = (const float*)d_in[2];
    const float* post_w = (const float*)d_in[3];
    const float* qw     = (const float*)d_in[4];
    const float* kw     = (const float*)d_in[5];
    const float* Wqkv   = (const float*)d_in[6];
    const float* Wo     = (const float*)d_in[7];
    const float* Wg     = (const float*)d_in[8];
    const float* gbias  = (const float*)d_in[9];
    const float* Wgu    = (const float*)d_in[10];
    const float* Wd     = (const float*)d_in[11];
    const float* Wgu_sh = (const float*)d_in[12];
    const float* Wd_sh  = (const float*)d_in[13];
    const int*   pos    = (const int*)d_in[14];
    float* out = (float*)d_out;

    float* resid = (out_size >= 2 * T_ * H_) ? (out + (size_t)T_ * H_) : nullptr;

    const int ATTN_SMEM = 16384 * 4 + 64 * 68 * 8;
    cudaFuncSetAttribute(attn_kernel, cudaFuncAttributeMaxDynamicSharedMemorySize, ATTN_SMEM);
    cudaFuncSetAttribute(gemm_qkv_kernel, cudaFuncAttributeMaxDynamicSharedMemorySize, GEMM_SMEM_BYTES);
    cudaFuncSetAttribute(gemm_o_kernel, cudaFuncAttributeMaxDynamicSharedMemorySize, GEMM_SMEM_BYTES);
    cudaFuncSetAttribute(gemm_gus_kernel, cudaFuncAttributeMaxDynamicSharedMemorySize, GEMM_SMEM_BYTES);
    cudaFuncSetAttribute(moe_gemm1_kernel, cudaFuncAttributeMaxDynamicSharedMemorySize, GEMM_SMEM_BYTES);
    cudaFuncSetAttribute(moe_gemm2_kernel, cudaFuncAttributeMaxDynamicSharedMemorySize, GEMM_SMEM_BYTES);
    cudaFuncSetAttribute(gemm_final_kernel, cudaFuncAttributeMaxDynamicSharedMemorySize, GEMM_SMEM_BYTES);

    add_rms_kernel<<<T_, 256>>>(hs, res, in_w, resid);
    gemm_qkv_kernel<<<dim3(QW_ / 64, T_ / 128), 256, GEMM_SMEM_BYTES>>>(Wqkv);
    qknorm_rope_kernel<<<(T_ * (NH_ + NKV_)) / 8, 256>>>(pos, qw, kw);
    attn_kernel<<<dim3(NH_, T_ / 128), 256, ATTN_SMEM>>>();
    gemm_o_kernel<<<dim3(H_ / 64, T_ / 128), 256, GEMM_SMEM_BYTES>>>(Wo, resid);
    rms2_kernel<<<T_, 256>>>(resid, post_w);
    zero_routed_kernel<<<T_ * H_ / 1024, 256>>>();
    init_kernel<<<1, 32>>>();
    router_kernel<<<T_, 32>>>(Wg, gbias);
    prefix_kernel<<<1, 1>>>();
    scatter_kernel<<<T_ / 256, 256>>>();
    moe_gemm1_kernel<<<dim3((2 * IM_) / 64, T_ / 128, E_), 256, GEMM_SMEM_BYTES>>>(Wgu);
    moe_gemm2_kernel<<<dim3(H_ / 64, T_ / 128, E_), 256, GEMM_SMEM_BYTES>>>(Wd);
    gemm_gus_kernel<<<dim3((2 * ISH_) / 64, T_ / 128), 256, GEMM_SMEM_BYTES>>>(Wgu_sh);
    gemm_final_kernel<<<dim3(H_ / 64, T_ / 128), 256, GEMM_SMEM_BYTES>>>(Wd_sh, out);
}

// round 17
// speedup vs baseline: 1.0506x; 1.0506x over previous
#include <cuda_runtime.h>
#include <math.h>

// ---------------- problem constants ----------------
constexpr int T_    = 2048;
constexpr int H_    = 1024;
constexpr int NH_   = 16;
constexpr int NKV_  = 4;
constexpr int HD_   = 64;
constexpr int E_    = 32;
constexpr int TOPK_ = 4;
constexpr int NG_   = 4;
constexpr int IM_   = 384;
constexpr int ISH_  = 384;
constexpr int QW_   = (NH_ + 2 * NKV_) * HD_;   // 1536
constexpr float EPS_ = 1e-5f;

// ---------------- scratch (50 MiB of device globals; aliased across phases) ------------
__device__ float g_hid[T_ * H_];                          // 8 MiB
__device__ float g_qkv[T_ * QW_];                         // 12 MiB
__device__ float g_gu [T_ * TOPK_ * 2 * IM_];             // 24 MiB
__device__ float g_gus[T_ * 2 * ISH_];                    // 6 MiB (shared-expert pre-act)
__device__ int   g_ids   [T_ * TOPK_];
__device__ float g_w     [T_ * TOPK_];
__device__ int   g_counts[E_];
__device__ int   g_offsets[E_ + 1];
__device__ int   g_cursor[E_];
__device__ int   g_tok   [T_ * TOPK_];
__device__ float g_wslot [T_ * TOPK_];

#define HID2   g_qkv                                   /* post-attn normed hidden */
#define GUS    g_gus                                   /* shared-expert pre-act   */
#define ROUTED g_hid                                   /* routed-expert accum     */
#define RES_FB (g_gu + 4194304)                        /* residual fallback       */

__constant__ float c_ropeinv[16] = {
    1.0f,                 0.5623413251903491f,  0.31622776601683794f, 0.17782794100389229f,
    0.1f,                 0.05623413251903491f, 0.031622776601683794f,0.017782794100389228f,
    0.01f,                0.005623413251903491f,0.0031622776601683794f,0.0017782794100389228f,
    0.001f,               0.0005623413251903491f,0.00031622776601683794f,0.00017782794100389227f
};

// ---------------- helpers ----------------
#define Z4 make_float4(0.f, 0.f, 0.f, 0.f)
typedef unsigned long long u64;

__device__ __forceinline__ float dot4(float4 a, float4 b) {
    return fmaf(a.x, b.x, fmaf(a.y, b.y, fmaf(a.z, b.z, a.w * b.w)));
}
__device__ __forceinline__ float4 add4(float4 a, float4 b) {
    return make_float4(a.x + b.x, a.y + b.y, a.z + b.z, a.w + b.w);
}
__device__ __forceinline__ float silu_mul(float g, float u) {
    return (g / (1.f + __expf(-g))) * u;
}
__device__ __forceinline__ float4 silu4(float4 g, float4 u) {
    return make_float4(silu_mul(g.x, u.x), silu_mul(g.y, u.y),
                       silu_mul(g.z, u.z), silu_mul(g.w, u.w));
}
// ---- packed f32x2 ops ----
__device__ __forceinline__ void fma2p(u64& d, u64 a, u64 b) {
    asm("fma.rn.f32x2 %0, %1, %2, %0;" : "+l"(d) : "l"(a), "l"(b));
}
__device__ __forceinline__ u64 pack2(float x) {
    u64 r; unsigned int bb = __float_as_uint(x);
    asm("mov.b64 %0, {%1, %2};" : "=l"(r) : "r"(bb), "r"(bb));
    return r;
}
__device__ __forceinline__ u64 pack2f(float lo, float hi) {
    u64 r;
    asm("mov.b64 %0, {%1, %2};" : "=l"(r)
        : "r"(__float_as_uint(lo)), "r"(__float_as_uint(hi)));
    return r;
}
__device__ __forceinline__ float2 unpack2(u64 v) {
    unsigned int lo, hi;
    asm("mov.b64 {%0, %1}, %2;" : "=r"(lo), "=r"(hi) : "l"(v));
    return make_float2(__uint_as_float(lo), __uint_as_float(hi));
}
// ---- cp.async (LDGSTS) ----
__device__ __forceinline__ unsigned scvta(const void* p) {
    return (unsigned)__cvta_generic_to_shared(p);
}
__device__ __forceinline__ void cp_async16(unsigned saddr, const void* gptr) {
    asm volatile("cp.async.ca.shared.global [%0], [%1], 16;" :: "r"(saddr), "l"(gptr));
}
#define CP_COMMIT asm volatile("cp.async.commit_group;" ::: "memory");
#define CP_WAIT0  asm volatile("cp.async.wait_group 0;" ::: "memory");

// ---- static stream/event for fork-join overlap (created pre-main) ----
namespace {
struct AuxStream {
    cudaStream_t s2; cudaEvent_t ev1, ev2;
    AuxStream() {
        cudaStreamCreateWithFlags(&s2, cudaStreamNonBlocking);
        cudaEventCreateWithFlags(&ev1, cudaEventDisableTiming);
        cudaEventCreateWithFlags(&ev2, cudaEventDisableTiming);
        (void)cudaGetLastError();
    }
};
static AuxStream g_aux;
}

// ======== pipelined 128x64x16 SGEMM pieces (double-buffered, 1 sync/step) ========
#define GEMM_ACCUM \
    u64 c00=0,c01=0,c02=0,c03=0,c10=0,c11=0,c12=0,c13=0, \
        c20=0,c21=0,c22=0,c23=0,c30=0,c31=0,c32=0,c33=0;

#define GEMM_COMPUTE(Ab, Bb) \
    _Pragma("unroll") \
    for (int kk = 0; kk < 16; kk++) { \
        const u64* ap = reinterpret_cast<const u64*>((Ab) + kk * 128 + (ty << 3)); \
        u64 a0 = ap[0], a1 = ap[1], a2 = ap[2], a3 = ap[3]; \
        float4 bf = *reinterpret_cast<const float4*>((Bb) + kk * 64 + (tx << 2)); \
        u64 b0 = pack2(bf.x), b1 = pack2(bf.y), b2 = pack2(bf.z), b3 = pack2(bf.w); \
        fma2p(c00,a0,b0); fma2p(c01,a0,b1); fma2p(c02,a0,b2); fma2p(c03,a0,b3); \
        fma2p(c10,a1,b0); fma2p(c11,a1,b1); fma2p(c12,a1,b2); fma2p(c13,a1,b3); \
        fma2p(c20,a2,b0); fma2p(c21,a2,b1); fma2p(c22,a2,b2); fma2p(c23,a2,b3); \
        fma2p(c30,a3,b0); fma2p(c31,a3,b1); fma2p(c32,a3,b2); fma2p(c33,a3,b3); \
    }

#define STS_A(Ab) { \
    (Ab)[(ac + 0) * 128 + ar] = av0.x; (Ab)[(ac + 1) * 128 + ar] = av0.y; \
    (Ab)[(ac + 2) * 128 + ar] = av0.z; (Ab)[(ac + 3) * 128 + ar] = av0.w; \
    (Ab)[(ac + 4) * 128 + ar] = av1.x; (Ab)[(ac + 5) * 128 + ar] = av1.y; \
    (Ab)[(ac + 6) * 128 + ar] = av1.z; (Ab)[(ac + 7) * 128 + ar] = av1.w; }

#define GEMM_EPILOGUE(STORE_ROW) { \
    int rbase = m0 + (ty << 3); \
    { float2 x0=unpack2(c00), x1=unpack2(c01), x2=unpack2(c02), x3=unpack2(c03); \
      STORE_ROW(rbase + 0, make_float4(x0.x,x1.x,x2.x,x3.x)) \
      STORE_ROW(rbase + 1, make_float4(x0.y,x1.y,x2.y,x3.y)) } \
    { float2 x0=unpack2(c10), x1=unpack2(c11), x2=unpack2(c12), x3=unpack2(c13); \
      STORE_ROW(rbase + 2, make_float4(x0.x,x1.x,x2.x,x3.x)) \
      STORE_ROW(rbase + 3, make_float4(x0.y,x1.y,x2.y,x3.y)) } \
    { float2 x0=unpack2(c20), x1=unpack2(c21), x2=unpack2(c22), x3=unpack2(c23); \
      STORE_ROW(rbase + 4, make_float4(x0.x,x1.x,x2.x,x3.x)) \
      STORE_ROW(rbase + 5, make_float4(x0.y,x1.y,x2.y,x3.y)) } \
    { float2 x0=unpack2(c30), x1=unpack2(c31), x2=unpack2(c32), x3=unpack2(c33); \
      STORE_ROW(rbase + 6, make_float4(x0.x,x1.x,x2.x,x3.x)) \
      STORE_ROW(rbase + 7, make_float4(x0.y,x1.y,x2.y,x3.y)) } \
}

#define GEMM_PIPE_DECLS \
    __shared__ __align__(16) float As[2][16][128]; \
    __shared__ __align__(16) float Bs[2][16][64]; \
    int tid = threadIdx.x; \
    int tx = tid & 15, ty = tid >> 4; \
    int ar = tid >> 1, ac = (tid & 1) << 3; \
    int br = tid >> 4, bc = (tid & 15) << 2; \
    unsigned sB0 = scvta(&Bs[0][br][bc]); \
    unsigned sB1 = scvta(&Bs[1][br][bc]); \
    float* A0 = &As[0][0][0]; float* A1 = &As[1][0][0]; \
    float* B0 = &Bs[0][0][0]; float* B1 = &Bs[1][0][0]; \
    GEMM_ACCUM \
    float4 av0, av1;

#define GEMM_PIPE_LOOP(LOADA, BPTR, KCONST) \
    LOADA(0) \
    cp_async16(sB0, (BPTR) + (size_t)br * N + n0 + bc); \
    CP_COMMIT \
    STS_A(A0) \
    { \
        int cur = 0; \
        for (int k0 = 0; k0 < (KCONST); k0 += 16) { \
            CP_WAIT0 \
            __syncthreads(); \
            bool has = (k0 + 16) < (KCONST); \
            if (has) { \
                LOADA(k0 + 16) \
                cp_async16(cur ? sB0 : sB1, \
                           (BPTR) + (size_t)(k0 + 16 + br) * N + n0 + bc); \
                CP_COMMIT \
            } \
            if (cur) { GEMM_COMPUTE(A1, B1) } else { GEMM_COMPUTE(A0, B0) } \
            if (has) { if (cur) { STS_A(A0) } else { STS_A(A1) } } \
            cur ^= 1; \
        } \
    }

// ---------------- generic direct SGEMM: C = A@B (+D) ----------------
template <bool ADD>
__device__ __forceinline__ void gemm_body(const float* __restrict__ A, const float* __restrict__ B,
                                          float* __restrict__ C, const float* __restrict__ D,
                                          int M, int N, int K) {
    int n0 = blockIdx.x * 64;
    int m0 = blockIdx.y * 128;
    if (m0 >= M) return;
    GEMM_PIPE_DECLS
    #define LOADA_G(k0v) { \
        av0 = Z4; av1 = Z4; \
        if (m0 + ar < M) { \
            av0 = *reinterpret_cast<const float4*>(A + (size_t)(m0 + ar) * K + (k0v) + ac); \
            av1 = *reinterpret_cast<const float4*>(A + (size_t)(m0 + ar) * K + (k0v) + ac + 4); } }
    GEMM_PIPE_LOOP(LOADA_G, B, K)
    #undef LOADA_G
    int cc = n0 + (tx << 2);
    #define SROW(r, v) { int rr = (r); if (rr < M) { \
        float4 vv = v; \
        if (ADD) vv = add4(vv, *reinterpret_cast<const float4*>(D + (size_t)rr * N + cc)); \
        *reinterpret_cast<float4*>(C + (size_t)rr * N + cc) = vv; } }
    GEMM_EPILOGUE(SROW)
    #undef SROW
}

__global__ __launch_bounds__(256) void gemm_qkv_kernel(const float* __restrict__ Wqkv) {
    gemm_body<false>(g_hid, Wqkv, g_qkv, nullptr, T_, QW_, H_);
}
__global__ __launch_bounds__(256) void gemm_o_kernel(const float* __restrict__ Wo, float* __restrict__ p) {
    float* resid = (p != nullptr) ? p : RES_FB;
    gemm_body<true>(g_hid, Wo, resid, resid, T_, H_, H_);
}
__global__ __launch_bounds__(256) void gemm_gus_kernel(const float* __restrict__ Wgu_sh) {
    gemm_body<false>(HID2, Wgu_sh, GUS, nullptr, T_, 2 * ISH_, H_);
}

// ---------------- MoE GEMM1: gu[slot,768] = HID2[tok] @ Wgu[e] ----------------
__global__ __launch_bounds__(256)
void moe_gemm1_kernel(const float* __restrict__ Wgu) {
    int e = blockIdx.z;
    int base = g_offsets[e];
    int ne = g_offsets[e + 1] - base;
    int m0 = blockIdx.y * 128;
    if (m0 >= ne) return;
    int n0 = blockIdx.x * 64;
    const int N = 2 * IM_, K = H_;
    const float* B = Wgu + (size_t)e * K * N;
    __shared__ int rowtok[128];
    if (threadIdx.x < 128)
        rowtok[threadIdx.x] = (m0 + threadIdx.x < ne) ? g_tok[base + m0 + threadIdx.x] : -1;
    __syncthreads();
    GEMM_PIPE_DECLS
    #define LOADA_M1(k0v) { \
        int tk = rowtok[ar]; \
        av0 = Z4; av1 = Z4; \
        if (tk >= 0) { \
            av0 = *reinterpret_cast<const float4*>(HID2 + (size_t)tk * K + (k0v) + ac); \
            av1 = *reinterpret_cast<const float4*>(HID2 + (size_t)tk * K + (k0v) + ac + 4); } }
    GEMM_PIPE_LOOP(LOADA_M1, B, K)
    #undef LOADA_M1
    int cc = n0 + (tx << 2);
    #define SROW(r, v) { int rr = (r); if (rr < ne) { \
        *reinterpret_cast<float4*>(g_gu + (size_t)(base + rr) * N + cc) = v; } }
    GEMM_EPILOGUE(SROW)
    #undef SROW
}

// ---- MoE GEMM2: routed[tok] += w * (silu(gu[:,:384])*gu[:,384:]) @ Wd[e] ----
__global__ __launch_bounds__(256)
void moe_gemm2_kernel(const float* __restrict__ Wd) {
    int e = blockIdx.z;
    int base = g_offsets[e];
    int ne = g_offsets[e + 1] - base;
    int m0 = blockIdx.y * 128;
    if (m0 >= ne) return;
    int n0 = blockIdx.x * 64;
    const int N = H_, K = IM_;
    const float* B = Wd + (size_t)e * K * N;
    __shared__ int   s_tok[128];
    __shared__ float s_wt[128];
    if (threadIdx.x < 128) {
        bool v = (m0 + threadIdx.x < ne);
        s_tok[threadIdx.x] = v ? g_tok[base + m0 + threadIdx.x] : -1;
        s_wt[threadIdx.x]  = v ? g_wslot[base + m0 + threadIdx.x] : 0.f;
    }
    __syncthreads();
    GEMM_PIPE_DECLS
    #define LOADA_M2(k0v) { \
        av0 = Z4; av1 = Z4; \
        if (m0 + ar < ne) { \
            const float* gub = g_gu + (size_t)(base + m0 + ar) * (2 * IM_); \
            float4 gg0 = *reinterpret_cast<const float4*>(gub + (k0v) + ac); \
            float4 gg1 = *reinterpret_cast<const float4*>(gub + (k0v) + ac + 4); \
            float4 uu0 = *reinterpret_cast<const float4*>(gub + IM_ + (k0v) + ac); \
            float4 uu1 = *reinterpret_cast<const float4*>(gub + IM_ + (k0v) + ac + 4); \
            av0 = silu4(gg0, uu0); av1 = silu4(gg1, uu1); } }
    GEMM_PIPE_LOOP(LOADA_M2, B, K)
    #undef LOADA_M2
    int cc = n0 + (tx << 2);
    #define SROW(r, v) { int slo = (r) - m0; \
        if (m0 + slo < ne) { \
            int tok = s_tok[slo]; float w = s_wt[slo]; float4 vv = v; \
            float* dst = ROUTED + (size_t)tok * N + cc; \
            atomicAdd(dst + 0, w * vv.x); atomicAdd(dst + 1, w * vv.y); \
            atomicAdd(dst + 2, w * vv.z); atomicAdd(dst + 3, w * vv.w); } }
    GEMM_EPILOGUE(SROW)
    #undef SROW
}

// ---- final GEMM: out = (silu(gus)*u) @ Wd_sh + routed ----
__global__ __launch_bounds__(256)
void gemm_final_kernel(const float* __restrict__ Wd_sh, float* __restrict__ out) {
    const int N = H_, K = ISH_;
    int n0 = blockIdx.x * 64;
    int m0 = blockIdx.y * 128;
    GEMM_PIPE_DECLS
    #define LOADA_F(k0v) { \
        const float* gub = GUS + (size_t)(m0 + ar) * (2 * ISH_); \
        float4 gg0 = *reinterpret_cast<const float4*>(gub + (k0v) + ac); \
        float4 gg1 = *reinterpret_cast<const float4*>(gub + (k0v) + ac + 4); \
        float4 uu0 = *reinterpret_cast<const float4*>(gub + ISH_ + (k0v) + ac); \
        float4 uu1 = *reinterpret_cast<const float4*>(gub + ISH_ + (k0v) + ac + 4); \
        av0 = silu4(gg0, uu0); av1 = silu4(gg1, uu1); }
    GEMM_PIPE_LOOP(LOADA_F, Wd_sh, K)
    #undef LOADA_F
    int cc = n0 + (tx << 2);
    #define SROW(r, v) { int rr = (r); \
        float4 vv = add4(v, *reinterpret_cast<const float4*>(ROUTED + (size_t)rr * N + cc)); \
        *reinterpret_cast<float4*>(out + (size_t)rr * N + cc) = vv; }
    GEMM_EPILOGUE(SROW)
    #undef SROW
}

// ---------------- step 1: residual add + input RMSNorm ----------------
__global__ void add_rms_kernel(const float* __restrict__ a, const float* __restrict__ b,
                               const float* __restrict__ w, float* __restrict__ p) {
    float* resid = (p != nullptr) ? p : RES_FB;
    int t = blockIdx.x;
    int i = threadIdx.x;
    float4 av = reinterpret_cast<const float4*>(a + (size_t)t * H_)[i];
    float4 bv = reinterpret_cast<const float4*>(b + (size_t)t * H_)[i];
    float4 r  = add4(av, bv);
    reinterpret_cast<float4*>(resid + (size_t)t * H_)[i] = r;
    float ss = dot4(r, r);
    __shared__ float red[8];
    __shared__ float s_rs;
    for (int o = 16; o > 0; o >>= 1) ss += __shfl_down_sync(0xffffffffu, ss, o);
    if ((threadIdx.x & 31) == 0) red[threadIdx.x >> 5] = ss;
    __syncthreads();
    if (threadIdx.x == 0) {
        float tot = 0.f;
        #pragma unroll
        for (int k = 0; k < 8; k++) tot += red[k];
        s_rs = rsqrtf(tot / (float)H_ + EPS_);
    }
    __syncthreads();
    float rs = s_rs;
    float4 wv = reinterpret_cast<const float4*>(w)[i];
    float4 o4 = make_float4(r.x * rs * wv.x, r.y * rs * wv.y, r.z * rs * wv.z, r.w * rs * wv.w);
    reinterpret_cast<float4*>(g_hid + (size_t)t * H_)[i] = o4;
}

// ---------------- step 6: post-attn RMSNorm + fused ROUTED zero + router init ----------
__global__ void rms2_kernel(const float* __restrict__ p, const float* __restrict__ w) {
    const float* x = (p != nullptr) ? p : RES_FB;
    int t = blockIdx.x;
    int i = threadIdx.x;
    float4 r = reinterpret_cast<const float4*>(x + (size_t)t * H_)[i];
    // fused: zero routed accumulator (g_hid is dead here) and router counters
    reinterpret_cast<float4*>(ROUTED + (size_t)t * H_)[i] = Z4;
    if (t == 0 && i < E_) { g_counts[i] = 0; g_cursor[i] = 0; }
    float ss = dot4(r, r);
    __shared__ float red[8];
    __shared__ float s_rs;
    for (int o = 16; o > 0; o >>= 1) ss += __shfl_down_sync(0xffffffffu, ss, o);
    if ((threadIdx.x & 31) == 0) red[threadIdx.x >> 5] = ss;
    __syncthreads();
    if (threadIdx.x == 0) {
        float tot = 0.f;
        #pragma unroll
        for (int k = 0; k < 8; k++) tot += red[k];
        s_rs = rsqrtf(tot / (float)H_ + EPS_);
    }
    __syncthreads();
    float rs = s_rs;
    float4 wv = reinterpret_cast<const float4*>(w)[i];
    float4 o4 = make_float4(r.x * rs * wv.x, r.y * rs * wv.y, r.z * rs * wv.z, r.w * rs * wv.w);
    reinterpret_cast<float4*>(HID2 + (size_t)t * H_)[i] = o4;
}

// ---------------- step 3: QK RMSNorm + RoPE ----------------
__global__ void qknorm_rope_kernel(const int* __restrict__ positions,
                                   const float* __restrict__ qw,
                                   const float* __restrict__ kw) {
    int warp = (blockIdx.x * blockDim.x + threadIdx.x) >> 5;
    int lane = threadIdx.x & 31;
    int total = T_ * (NH_ + NKV_);
    if (warp >= total) return;
    int t = warp / (NH_ + NKV_);
    int h = warp % (NH_ + NKV_);
    float* base = g_qkv + (size_t)t * QW_ + h * HD_;
    float xa = base[lane];
    float xb = base[lane + 32];
    float ss = xa * xa + xb * xb;
    for (int o = 16; o > 0; o >>= 1) ss += __shfl_xor_sync(0xffffffffu, ss, o);
    float rs = rsqrtf(ss / (float)HD_ + EPS_);
    const float* w = (h < NH_) ? qw : kw;
    xa *= rs * w[lane];
    xb *= rs * w[lane + 32];
    int i = lane & 15;
    float ang = (float)positions[t] * c_ropeinv[i];
    float kf = __int2float_rn(__float2int_rn(ang * 0.15915494309189535f));
    float r = fmaf(kf, -6.28125f, ang);
    r = fmaf(kf, -1.9353071795864769e-3f, r);
    float c = __cosf(r);
    float s = __sinf(r);
    float partner = __shfl_xor_sync(0xffffffffu, xa, 16);
    float res = (lane < 16) ? (xa * c - partner * s) : (partner * s + xa * c);
    base[lane] = res;
    base[lane + 32] = xb;
}

// ---------------- step 4: causal attention — two tiled GEMMs, 2 CTAs/SM ---------------
__global__ __launch_bounds__(256, 2)
void attn_kernel() {
    extern __shared__ float sm[];
    float* Qs = sm;
    float* Ks = sm + 8192;
    float* Vs = sm + 12288;
    u64*   Pp = reinterpret_cast<u64*>(sm + 16384);

    int h  = blockIdx.x;
    int qb = (gridDim.y - 1) - blockIdx.y;
    int kh = h >> 2;
    int tid = threadIdx.x;
    int tx = tid & 15, ty = tid >> 4;
    int qbase = qb * 128;

    {
        int q  = tid >> 1;
        int dh = (tid & 1) << 5;
        const float4* src = reinterpret_cast<const float4*>(
            g_qkv + (size_t)(qbase + q) * QW_ + h * HD_ + dh);
        #pragma unroll
        for (int i = 0; i < 8; i++) {
            float4 v = src[i];
            int d = dh + (i << 2);
            Qs[(d+0)*128 + q] = v.x; Qs[(d+1)*128 + q] = v.y;
            Qs[(d+2)*128 + q] = v.z; Qs[(d+3)*128 + q] = v.w;
        }
    }
    u64 o00=0,o01=0,o02=0,o03=0,o10=0,o11=0,o12=0,o13=0,
        o20=0,o21=0,o22=0,o23=0,o30=0,o31=0,o32=0,o33=0;
    float l0=0,l1=0,l2=0,l3=0,l4=0,l5=0,l6=0,l7=0;

    int ntiles = 2 * qb + 2;
    for (int tile = 0; tile < ntiles; tile++) {
        int s0 = tile * 64;
        __syncthreads();
        {
            int kl = tid & 63;
            int db = (tid >> 6) << 4;
            const float* kr = g_qkv + (size_t)(s0 + kl) * QW_ + NH_ * HD_ + kh * HD_ + db;
            #pragma unroll
            for (int i = 0; i < 4; i++) {
                float4 v = *reinterpret_cast<const float4*>(kr + (i << 2));
                int d = db + (i << 2);
                Ks[(d+0)*64+kl]=v.x; Ks[(d+1)*64+kl]=v.y; Ks[(d+2)*64+kl]=v.z; Ks[(d+3)*64+kl]=v.w;
            }
            const float* vr = kr + NKV_ * HD_;
            #pragma unroll
            for (int i = 0; i < 4; i++) {
                float4 v = *reinterpret_cast<const float4*>(vr + (i << 2));
                *reinterpret_cast<float4*>(&Vs[kl * 64 + db + (i << 2)]) = v;
            }
        }
        __syncthreads();
        u64 s00=0,s01=0,s02=0,s03=0,s10=0,s11=0,s12=0,s13=0,
            s20=0,s21=0,s22=0,s23=0,s30=0,s31=0,s32=0,s33=0;
        #pragma unroll 4
        for (int kk = 0; kk < 64; kk++) {
            const u64* ap = reinterpret_cast<const u64*>(Qs + kk * 128 + (ty << 3));
            u64 a0 = ap[0], a1 = ap[1], a2 = ap[2], a3 = ap[3];
            const float4 bf = *reinterpret_cast<const float4*>(Ks + kk * 64 + (tx << 2));
            u64 b0 = pack2(bf.x), b1 = pack2(bf.y), b2 = pack2(bf.z), b3 = pack2(bf.w);
            fma2p(s00,a0,b0); fma2p(s01,a0,b1); fma2p(s02,a0,b2); fma2p(s03,a0,b3);
            fma2p(s10,a1,b0); fma2p(s11,a1,b1); fma2p(s12,a1,b2); fma2p(s13,a1,b3);
            fma2p(s20,a2,b0); fma2p(s21,a2,b1); fma2p(s22,a2,b2); fma2p(s23,a2,b3);
            fma2p(s30,a3,b0); fma2p(s31,a3,b1); fma2p(s32,a3,b2); fma2p(s33,a3,b3);
        }
        int kg = s0 + (tx << 2);
        #define DOQP(qp, sA, sB, sC, sD, rA, rB) { \
            int qg0 = qbase + (ty << 3) + 2 * qp; int qg1 = qg0 + 1; \
            float2 e0 = unpack2(sA), e1 = unpack2(sB), e2 = unpack2(sC), e3 = unpack2(sD); \
            float p00 = (kg+0 <= qg0) ? __expf(fmaf(e0.x, 0.125f, -8.f)) : 0.f; \
            float p01 = (kg+1 <= qg0) ? __expf(fmaf(e1.x, 0.125f, -8.f)) : 0.f; \
            float p02 = (kg+2 <= qg0) ? __expf(fmaf(e2.x, 0.125f, -8.f)) : 0.f; \
            float p03 = (kg+3 <= qg0) ? __expf(fmaf(e3.x, 0.125f, -8.f)) : 0.f; \
            float p10 = (kg+0 <= qg1) ? __expf(fmaf(e0.y, 0.125f, -8.f)) : 0.f; \
            float p11 = (kg+1 <= qg1) ? __expf(fmaf(e1.y, 0.125f, -8.f)) : 0.f; \
            float p12 = (kg+2 <= qg1) ? __expf(fmaf(e2.y, 0.125f, -8.f)) : 0.f; \
            float p13 = (kg+3 <= qg1) ? __expf(fmaf(e3.y, 0.125f, -8.f)) : 0.f; \
            rA += (p00 + p01) + (p02 + p03); \
            rB += (p10 + p11) + (p12 + p13); \
            u64* dst = Pp + ((ty << 2) + qp) * 68 + (tx << 2); \
            dst[0] = pack2f(p00, p10); dst[1] = pack2f(p01, p11); \
            dst[2] = pack2f(p02, p12); dst[3] = pack2f(p03, p13); }
        float r0=0,r1=0,r2=0,r3=0,r4=0,r5=0,r6=0,r7=0;
        DOQP(0, s00, s01, s02, s03, r0, r1)
        DOQP(1, s10, s11, s12, s13, r2, r3)
        DOQP(2, s20, s21, s22, s23, r4, r5)
        DOQP(3, s30, s31, s32, s33, r6, r7)
        #undef DOQP
        #pragma unroll
        for (int off = 1; off < 16; off <<= 1) {
            r0 += __shfl_xor_sync(0xffffffffu, r0, off);
            r1 += __shfl_xor_sync(0xffffffffu, r1, off);
            r2 += __shfl_xor_sync(0xffffffffu, r2, off);
            r3 += __shfl_xor_sync(0xffffffffu, r3, off);
            r4 += __shfl_xor_sync(0xffffffffu, r4, off);
            r5 += __shfl_xor_sync(0xffffffffu, r5, off);
            r6 += __shfl_xor_sync(0xffffffffu, r6, off);
            r7 += __shfl_xor_sync(0xffffffffu, r7, off);
        }
        l0 += r0; l1 += r1; l2 += r2; l3 += r3;
        l4 += r4; l5 += r5; l6 += r6; l7 += r7;
        __syncthreads();
        #pragma unroll 4
        for (int s = 0; s < 64; s++) {
            u64 a0 = Pp[((ty << 2) + 0) * 68 + s];
            u64 a1 = Pp[((ty << 2) + 1) * 68 + s];
            u64 a2 = Pp[((ty << 2) + 2) * 68 + s];
            u64 a3 = Pp[((ty << 2) + 3) * 68 + s];
            const float4 vf = *reinterpret_cast<const float4*>(&Vs[s * 64 + (tx << 2)]);
            u64 b0 = pack2(vf.x), b1 = pack2(vf.y), b2 = pack2(vf.z), b3 = pack2(vf.w);
            fma2p(o00,a0,b0); fma2p(o01,a0,b1); fma2p(o02,a0,b2); fma2p(o03,a0,b3);
            fma2p(o10,a1,b0); fma2p(o11,a1,b1); fma2p(o12,a1,b2); fma2p(o13,a1,b3);
            fma2p(o20,a2,b0); fma2p(o21,a2,b1); fma2p(o22,a2,b2); fma2p(o23,a2,b3);
            fma2p(o30,a3,b0); fma2p(o31,a3,b1); fma2p(o32,a3,b2); fma2p(o33,a3,b3);
        }
    }
    float i0 = 1.f/l0, i1 = 1.f/l1, i2 = 1.f/l2, i3 = 1.f/l3;
    float i4 = 1.f/l4, i5 = 1.f/l5, i6 = 1.f/l6, i7 = 1.f/l7;
    int cbase = h * HD_ + (tx << 2);
    #define OUTQP(qp, uA, uB, uC, uD, iA, iB) { \
        float2 e0 = unpack2(uA), e1 = unpack2(uB), e2 = unpack2(uC), e3 = unpack2(uD); \
        int rA = qbase + (ty << 3) + 2 * qp; \
        *reinterpret_cast<float4*>(g_hid + (size_t)rA * H_ + cbase) = \
            make_float4(e0.x * iA, e1.x * iA, e2.x * iA, e3.x * iA); \
        *reinterpret_cast<float4*>(g_hid + (size_t)(rA + 1) * H_ + cbase) = \
            make_float4(e0.y * iB, e1.y * iB, e2.y * iB, e3.y * iB); }
    OUTQP(0, o00, o01, o02, o03, i0, i1)
    OUTQP(1, o10, o11, o12, o13, i2, i3)
    OUTQP(2, o20, o21, o22, o23, i4, i5)
    OUTQP(3, o30, o31, o32, o33, i6, i7)
    #undef OUTQP
}

// ---------------- router / routing infrastructure ----------------
__global__ void router_kernel(const float* __restrict__ Wg, const float* __restrict__ gbias) {
    int t = blockIdx.x;
    int lane = threadIdx.x;
    __shared__ float hsh[H_];
    for (int i = lane; i < H_; i += 32) hsh[i] = HID2[(size_t)t * H_ + i];
    __syncwarp();
    float acc = 0.f;
    for (int hh = 0; hh < H_; hh++) acc = fmaf(hsh[hh], Wg[hh * E_ + lane], acc);
    float scr = 1.f / (1.f + __expf(-acc));
    float sfc = scr + gbias[lane];
    __shared__ float s_scr[E_], s_sfc[E_], s_tmp[E_], s_gs[NG_];
    s_scr[lane] = scr; s_sfc[lane] = sfc;
    __syncwarp();
    if (lane == 0) {
        for (int g = 0; g < NG_; g++) {
            float m1 = -INFINITY, m2 = -INFINITY;
            for (int j = 0; j < E_ / NG_; j++) {
                float v = s_sfc[g * (E_ / NG_) + j];
                if (v > m1) { m2 = m1; m1 = v; } else if (v > m2) m2 = v;
            }
            s_gs[g] = m1 + m2;
        }
        int g1 = 0;
        for (int g = 1; g < NG_; g++) if (s_gs[g] > s_gs[g1]) g1 = g;
        s_gs[g1] = -INFINITY;
        int g2 = 0;
        for (int g = 1; g < NG_; g++) if (s_gs[g] > s_gs[g2]) g2 = g;
        for (int e = 0; e < E_; e++) {
            int g = e / (E_ / NG_);
            s_tmp[e] = (g == g1 || g == g2) ? s_sfc[e] : -INFINITY;
        }
        float wsum = 0.f;
        #pragma unroll
        for (int k = 0; k < TOPK_; k++) {
            int best = 0; float bv = s_tmp[0];
            for (int e = 1; e < E_; e++) if (s_tmp[e] > bv) { bv = s_tmp[e]; best = e; }
            s_tmp[best] = -INFINITY;
            wsum += s_scr[best];
            g_ids[t * TOPK_ + k] = best;
            atomicAdd(&g_counts[best], 1);
        }
        float rw = 1.f / wsum;
        #pragma unroll
        for (int k = 0; k < TOPK_; k++)
            g_w[t * TOPK_ + k] = s_scr[g_ids[t * TOPK_ + k]] * rw;
    }
}

__global__ void prefix_kernel() {
    if (threadIdx.x == 0) {
        int s = 0;
        for (int e = 0; e < E_; e++) { g_offsets[e] = s; s += g_counts[e]; }
        g_offsets[E_] = s;
    }
}

__global__ void scatter_kernel() {
    int t = blockIdx.x * blockDim.x + threadIdx.x;
    if (t >= T_) return;
    #pragma unroll
    for (int k = 0; k < TOPK_; k++) {
        int e = g_ids[t * TOPK_ + k];
        int p = atomicAdd(&g_cursor[e], 1);
        int slot = g_offsets[e] + p;
        g_tok[slot] = t;
        g_wslot[slot] = g_w[t * TOPK_ + k];
    }
}

// ---------------- host launch ----------------
extern "C" void kernel_launch(void* const* d_in, const int* in_sizes, int n_in,
                              void* d_out, int out_size) {
    const float* hs     = (const float*)d_in[0];
    const float* res    = (const float*)d_in[1];
    const float* in_w   = (const float*)d_in[2];
    const float* post_w = (const float*)d_in[3];
    const float* qw     = (const float*)d_in[4];
    const float* kw     = (const float*)d_in[5];
    const float* Wqkv   = (const float*)d_in[6];
    const float* Wo     = (const float*)d_in[7];
    const float* Wg     = (const float*)d_in[8];
    const float* gbias  = (const float*)d_in[9];
    const float* Wgu    = (const float*)d_in[10];
    const float* Wd     = (const float*)d_in[11];
    const float* Wgu_sh = (const float*)d_in[12];
    const float* Wd_sh  = (const float*)d_in[13];
    const int*   pos    = (const int*)d_in[14];
    float* out = (float*)d_out;

    float* resid = (out_size >= 2 * T_ * H_) ? (out + (size_t)T_ * H_) : nullptr;

    const int ATTN_SMEM = 16384 * 4 + 64 * 68 * 8;
    cudaFuncSetAttribute(attn_kernel, cudaFuncAttributeMaxDynamicSharedMemorySize, ATTN_SMEM);

    add_rms_kernel<<<T_, 256>>>(hs, res, in_w, resid);
    gemm_qkv_kernel<<<dim3(QW_ / 64, T_ / 128), 256>>>(Wqkv);
    qknorm_rope_kernel<<<(T_ * (NH_ + NKV_)) / 8, 256>>>(pos, qw, kw);
    attn_kernel<<<dim3(NH_, T_ / 128), 256, ATTN_SMEM>>>();
    gemm_o_kernel<<<dim3(H_ / 64, T_ / 128), 256>>>(Wo, resid);
    // rms2 fuses: HID2 compute + ROUTED zero + router counter init
    rms2_kernel<<<T_, 256>>>(resid, post_w);

    // fork: shared-expert GEMM overlaps the routed-expert pipeline
    cudaEventRecord(g_aux.ev1, 0);
    cudaStreamWaitEvent(g_aux.s2, g_aux.ev1, 0);
    gemm_gus_kernel<<<dim3((2 * ISH_) / 64, T_ / 128), 256, 0, g_aux.s2>>>(Wgu_sh);
    cudaEventRecord(g_aux.ev2, g_aux.s2);

    router_kernel<<<T_, 32>>>(Wg, gbias);
    prefix_kernel<<<1, 1>>>();
    scatter_kernel<<<T_ / 256, 256>>>();
    moe_gemm1_kernel<<<dim3((2 * IM_) / 64, T_ / 128, E_), 256>>>(Wgu);
    moe_gemm2_kernel<<<dim3(H_ / 64, T_ / 128, E_), 256>>>(Wd);

    // join: final needs both GUS (s2) and ROUTED (stream 0)
    cudaStreamWaitEvent(0, g_aux.ev2, 0);
    gemm_final_kernel<<<dim3(H_ / 64, T_ / 128), 256>>>(Wd_sh, out);
}